// round 13
// baseline (speedup 1.0000x reference)
#include <cuda_runtime.h>
#include <cstdint>

// Problem constants
#define N_TOKENS 131072
#define E_DIM    128
#define KCB      1024
#define NQ       4

// Tiling
#define T_BLK    128
#define NTHREADS 512
#define CHUNK    128
#define NCHUNKS  8
#define NBLOCKS  1024
#define NCAND    6

#define XS_PITCH 129        // fp32 residual [t][k] (scalar access only)
#define XQ_PITCH 129        // fp32 x_q [t][k]
#define QPITCH   36         // int8 rows as 36 words (144B): uint4-aligned, LDS conflict-free

// Output layout (float32): x_q [N,128] | mean_loss [1] | all_indices [N,4]
#define OUT_XQ_ELEMS   ((size_t)N_TOKENS * E_DIM)
#define OUT_LOSS_OFF   OUT_XQ_ELEMS
#define OUT_IDX_OFF    (OUT_XQ_ELEMS + 1)

// Smem layout (float/word indices)
#define OFF_XS    0                     // 16512
#define OFF_XQ    16512                 // 16512
#define OFF_RR    33024                 // 128
#define OFF_LOSS  33152                 // 128
#define OFF_SA    33280                 // 128  inv_sa = maxabs/127
#define OFF_S127  33408                 // 128  s127   = 127/maxabs
#define OFF_CCS   33536                 // 128
#define OFF_RSS   33664                 // 128
#define OFF_CAND  33792                 // 768 ints
#define OFF_DEM   34560                 // 768
#define OFF_QA    35328                 // 4608 words (16B aligned)
#define OFF_QB    39936                 // 4608 words
#define SM_TOTAL_F 44544
#define SMEM_BYTES (SM_TOTAL_F * 4)     // 178176 B

__device__ float    g_cc[NQ * KCB];                   // gold ||c||^2 (NEON emu)
__device__ float    g_rs[NQ * KCB];                   // maxabs_c / 127
__device__ uint32_t g_qb[NQ * NCHUNKS * CHUNK * 32];  // packed int8 codebook, [s][ch][row][32w]
__device__ float    g_partials[NBLOCKS];

// NEON-style vectorized sum-of-squares (XLA:CPU fast-math reduce) — VERIFIED bitwise vs ref.
__device__ __forceinline__ float neon_sumsq(const float* v) {
    float a0=0.f,a1=0.f,a2=0.f,a3=0.f,b0=0.f,b1=0.f,b2=0.f,b3=0.f;
    #pragma unroll 4
    for (int k = 0; k < E_DIM; k += 8) {
        float v0=v[k],v1=v[k+1],v2=v[k+2],v3=v[k+3],v4=v[k+4],v5=v[k+5],v6=v[k+6],v7=v[k+7];
        a0=__fmaf_rn(v0,v0,a0); a1=__fmaf_rn(v1,v1,a1); a2=__fmaf_rn(v2,v2,a2); a3=__fmaf_rn(v3,v3,a3);
        b0=__fmaf_rn(v4,v4,b0); b1=__fmaf_rn(v5,v5,b1); b2=__fmaf_rn(v6,v6,b2); b3=__fmaf_rn(v7,v7,b3);
    }
    float s0=__fadd_rn(a0,b0), s1=__fadd_rn(a1,b1), s2=__fadd_rn(a2,b2), s3=__fadd_rn(a3,b3);
    return __fadd_rn(__fadd_rn(s0,s1), __fadd_rn(s2,s3));
}

__device__ __forceinline__ uint32_t pack4(const float* v, float s) {
    int b0 = __float2int_rn(v[0] * s) & 255;
    int b1 = __float2int_rn(v[1] * s) & 255;
    int b2 = __float2int_rn(v[2] * s) & 255;
    int b3 = __float2int_rn(v[3] * s) & 255;
    return (uint32_t)(b0 | (b1 << 8) | (b2 << 16) | (b3 << 24));
}

__global__ void prep_kernel(const float* __restrict__ cb) {
    int c = blockIdx.x * blockDim.x + threadIdx.x;   // one codeword per thread
    if (c < NQ * KCB) {
        const float* row = cb + (size_t)c * E_DIM;
        g_cc[c] = neon_sumsq(row);                    // gold
        float ma = 0.0f;
        #pragma unroll 8
        for (int k = 0; k < E_DIM; ++k) ma = fmaxf(ma, fabsf(row[k]));
        ma = fmaxf(ma, 1e-30f);
        g_rs[c] = ma * (1.0f / 127.0f);
        float s = 127.0f / ma;
        int sdx = c / KCB, cw = c % KCB;
        uint32_t* dst = g_qb + (size_t)(sdx * KCB + cw) * 32;
        #pragma unroll 8
        for (int w = 0; w < 32; ++w) dst[w] = pack4(row + w * 4, s);
    }
}

__global__ void __launch_bounds__(NTHREADS, 1)
rvq_kernel(const float* __restrict__ x, const float* __restrict__ cb, float* __restrict__ out)
{
    extern __shared__ float sm[];
    float* xs      = sm + OFF_XS;
    float* xq      = sm + OFF_XQ;
    float* rr      = sm + OFF_RR;
    float* lossbuf = sm + OFF_LOSS;
    float* sainv   = sm + OFF_SA;
    float* s127    = sm + OFF_S127;
    float* ccs     = sm + OFF_CCS;
    float* rss     = sm + OFF_RSS;
    int*   cand    = (int*)(sm + OFF_CAND);
    float* dem     = sm + OFF_DEM;
    int*   qa      = (int*)(sm + OFF_QA);
    int*   qb      = (int*)(sm + OFF_QB);
    // red aliases over QA/QB (dead after GEMM of a stage)
    float* red_d   = sm + OFF_QA;                    // [t][32]
    int*   red_i   = (int*)(sm + OFF_QA + 4096);     // [t][32]

    const int tid = threadIdx.x;
    const int tr  = tid & 31;      // token group: tokens tr*4..tr*4+3
    const int tc  = tid >> 5;      // warp -> cw group tc*8..tc*8+7
    const int t0  = blockIdx.x * T_BLK;

    // ---- Load x tile (row-major), zero xq/lossbuf
    {
        const float4* x4 = (const float4*)(x + (size_t)t0 * E_DIM);
        #pragma unroll
        for (int r = 0; r < 8; ++r) {
            int f = tid + NTHREADS * r;
            int t = f >> 5, k4 = f & 31;
            float4 v = x4[f];
            xs[t * XS_PITCH + k4 * 4 + 0] = v.x;
            xs[t * XS_PITCH + k4 * 4 + 1] = v.y;
            xs[t * XS_PITCH + k4 * 4 + 2] = v.z;
            xs[t * XS_PITCH + k4 * 4 + 3] = v.w;
        }
        for (int o = tid; o < T_BLK * XQ_PITCH; o += NTHREADS) xq[o] = 0.0f;
        if (tid < T_BLK) lossbuf[tid] = 0.0f;
    }

    for (int s = 0; s <= NQ; ++s) {
        __syncthreads();
        // ---- rr (gold NEON emu) + maxabs + loss
        if (tid < T_BLK) {
            const float* row = xs + tid * XS_PITCH;
            float a = neon_sumsq(row);
            rr[tid] = a;
            if (s > 0) lossbuf[tid] += a;
            float ma = 0.0f;
            #pragma unroll 8
            for (int k = 0; k < E_DIM; ++k) ma = fmaxf(ma, fabsf(row[k]));
            ma = fmaxf(ma, 1e-30f);
            sainv[tid] = ma * (1.0f / 127.0f);
            s127[tid]  = 127.0f / ma;
        }
        __syncthreads();
        if (s == NQ) break;

        // ---- quantize residual to int8 (selection only)
        {
            int t = tid & 127, ks = (tid >> 7) * 32;   // 32 elems/thread
            float sc = s127[t];
            const float* row = xs + t * XS_PITCH + ks;
            int* dst = qa + t * QPITCH + ks / 4;
            #pragma unroll 8
            for (int w = 0; w < 8; ++w) dst[w] = (int)pack4(row + w * 4, sc);
        }

        // per-thread top-2 across all chunks (per token i of 4)
        float d0[4], d1[4]; int i0[4], i1[4];
        #pragma unroll
        for (int i = 0; i < 4; ++i) {
            d0[i] = __int_as_float(0x7f800000); i0[i] = 0x7fffffff;
            d1[i] = __int_as_float(0x7f800000); i1[i] = 0x7fffffff;
        }

        // prefetch chunk 0 of B (2 uint4 per thread = 1024 total)
        uint4 pre0, pre1; float ccp = 0.f, rsp = 0.f;
        {
            const uint4* src = (const uint4*)(g_qb + (size_t)s * KCB * 32);
            pre0 = src[tid]; pre1 = src[tid + 512];
            if (tid < CHUNK) { ccp = g_cc[s * KCB + tid]; rsp = g_rs[s * KCB + tid]; }
        }

        for (int ch = 0; ch < NCHUNKS; ++ch) {
            // commit prefetched B to smem (row=idx>>3, seg=idx&7 -> pitch 36)
            {
                int idx0 = tid, idx1 = tid + 512;
                *(uint4*)(qb + (idx0 >> 3) * QPITCH + (idx0 & 7) * 4) = pre0;
                *(uint4*)(qb + (idx1 >> 3) * QPITCH + (idx1 & 7) * 4) = pre1;
                if (tid < CHUNK) { ccs[tid] = ccp; rss[tid] = rsp; }
            }
            __syncthreads();

            // prefetch next chunk
            if (ch + 1 < NCHUNKS) {
                const uint4* src = (const uint4*)(g_qb + ((size_t)s * KCB + (ch + 1) * CHUNK) * 32);
                pre0 = src[tid]; pre1 = src[tid + 512];
                if (tid < CHUNK) {
                    ccp = g_cc[s * KCB + (ch + 1) * CHUNK + tid];
                    rsp = g_rs[s * KCB + (ch + 1) * CHUNK + tid];
                }
            }

            // ---- int8 GEMM: 4 tok x 8 cw per thread, K=128 via dp4a
            int acc[4][8];
            #pragma unroll
            for (int i = 0; i < 4; ++i)
                #pragma unroll
                for (int j = 0; j < 8; ++j) acc[i][j] = 0;

            #pragma unroll
            for (int k4 = 0; k4 < 8; ++k4) {
                uint4 b[8];
                #pragma unroll
                for (int j = 0; j < 8; ++j)
                    b[j] = *(const uint4*)(qb + (tc * 8 + j) * QPITCH + k4 * 4);
                #pragma unroll
                for (int i = 0; i < 4; ++i) {
                    uint4 a = *(const uint4*)(qa + (tr * 4 + i) * QPITCH + k4 * 4);
                    #pragma unroll
                    for (int j = 0; j < 8; ++j) {
                        acc[i][j] = __dp4a((int)a.x, (int)b[j].x, acc[i][j]);
                        acc[i][j] = __dp4a((int)a.y, (int)b[j].y, acc[i][j]);
                        acc[i][j] = __dp4a((int)a.z, (int)b[j].z, acc[i][j]);
                        acc[i][j] = __dp4a((int)a.w, (int)b[j].w, acc[i][j]);
                    }
                }
            }

            // ---- selection epilogue: v = cc - 2*inv_sa*rs[c]*dot  (rr cancels)
            #pragma unroll
            for (int i = 0; i < 4; ++i) {
                float t2 = 2.0f * sainv[tr * 4 + i];
                #pragma unroll
                for (int j = 0; j < 8; ++j) {
                    int   cl = tc * 8 + j;
                    float v  = __fmaf_rn(-t2, rss[cl] * (float)acc[i][j], ccs[cl]);
                    int   c  = ch * CHUNK + cl;
                    bool b0 = (v < d0[i]);
                    bool b1 = (v < d1[i]);
                    if (b0)      { d1[i]=d0[i]; i1[i]=i0[i]; d0[i]=v; i0[i]=c; }
                    else if (b1) { d1[i]=v;     i1[i]=c; }
                }
            }
            __syncthreads();
        }

        // ---- dump per-thread top-2 (QA/QB dead -> red buffers)
        #pragma unroll
        for (int i = 0; i < 4; ++i) {
            int t = tr * 4 + i;
            red_d[t * 32 + tc * 2 + 0] = d0[i];
            red_d[t * 32 + tc * 2 + 1] = d1[i];
            red_i[t * 32 + tc * 2 + 0] = i0[i];
            red_i[t * 32 + tc * 2 + 1] = i1[i];
        }
        __syncthreads();

        // ---- merge 32 -> top-6 candidates
        if (tid < T_BLK) {
            float tv[NCAND]; int ti[NCAND];
            #pragma unroll
            for (int q = 0; q < NCAND; ++q) { tv[q] = __int_as_float(0x7f800000); ti[q] = 0x7fffffff; }
            for (int g = 0; g < 32; ++g) {
                float v = red_d[tid * 32 + g];
                int   c = red_i[tid * 32 + g];
                #pragma unroll
                for (int q = 0; q < NCAND; ++q) {
                    bool better = (v < tv[q]) || (v == tv[q] && c < ti[q]);
                    if (better) { float vt = tv[q]; int ct = ti[q]; tv[q] = v; ti[q] = c; v = vt; c = ct; }
                }
            }
            #pragma unroll
            for (int q = 0; q < NCAND; ++q) cand[tid * NCAND + q] = ti[q];
        }
        __syncthreads();

        // ---- gold refinement (seq-FMA dot, Eigen-consistent), 512 threads
        {
            int t = tid & 127, g = tid >> 7;
            float rrt = rr[t];
            #pragma unroll
            for (int rep = 0; rep < 2; ++rep) {
                int q = g + rep * 4;
                if (q >= NCAND) break;
                int c = cand[t * NCAND + q];
                const float* crow = cb + (size_t)(s * KCB + c) * E_DIM;
                float hs = 0.0f;
                #pragma unroll 16
                for (int k = 0; k < E_DIM; ++k)
                    hs = __fmaf_rn(xs[t * XS_PITCH + k], crow[k], hs);
                dem[t * NCAND + q] = __fadd_rn(__fsub_rn(rrt, __fmul_rn(2.0f, hs)), g_cc[s * KCB + c]);
            }
        }
        __syncthreads();

        // ---- pick winner (gold comparator) + straight-through update
        if (tid < T_BLK) {
            float bestv = 0.0f; int besti = -1;
            #pragma unroll
            for (int q = 0; q < NCAND; ++q) {
                int   c = cand[tid * NCAND + q];
                float v = dem[tid * NCAND + q];
                if (besti < 0 || v < bestv || (v == bestv && c < besti)) { bestv = v; besti = c; }
            }
            out[OUT_IDX_OFF + (size_t)(t0 + tid) * NQ + s] = (float)besti;

            const float4* qrow = (const float4*)(cb + (size_t)(s * KCB + besti) * E_DIM);
            #pragma unroll 4
            for (int k4 = 0; k4 < 32; ++k4) {
                float4 q4 = qrow[k4];
                #pragma unroll
                for (int m = 0; m < 4; ++m) {
                    int   k  = k4 * 4 + m;
                    float qv = (m == 0) ? q4.x : (m == 1) ? q4.y : (m == 2) ? q4.z : q4.w;
                    float r  = xs[tid * XS_PITCH + k];
                    float qt = __fadd_rn(r, __fsub_rn(qv, r));
                    xq[tid * XQ_PITCH + k] = __fadd_rn(xq[tid * XQ_PITCH + k], qt);
                    xs[tid * XS_PITCH + k] = __fsub_rn(r, qt);
                }
            }
        }
    }

    if (tid == 0) {
        float a = 0.0f;
        for (int t = 0; t < T_BLK; ++t) a += lossbuf[t];
        g_partials[blockIdx.x] = a;
    }

    {
        float* o = out + (size_t)t0 * E_DIM;
        for (int f = tid; f < T_BLK * E_DIM; f += NTHREADS)
            o[f] = xq[(f >> 7) * XQ_PITCH + (f & 127)];
    }
}

__global__ void finalize_kernel(float* __restrict__ out) {
    if (threadIdx.x == 0 && blockIdx.x == 0) {
        double a = 0.0;
        for (int i = 0; i < NBLOCKS; ++i) a += (double)g_partials[i];
        out[OUT_LOSS_OFF] = (float)(a * (0.25 / (4.0 * (double)N_TOKENS * (double)E_DIM)));
    }
}

extern "C" void kernel_launch(void* const* d_in, const int* in_sizes, int n_in,
                              void* d_out, int out_size) {
    (void)in_sizes; (void)n_in; (void)out_size;
    const float* x  = (const float*)d_in[0];
    const float* cb = (const float*)d_in[1];
    float* out = (float*)d_out;

    cudaFuncSetAttribute(rvq_kernel, cudaFuncAttributeMaxDynamicSharedMemorySize, SMEM_BYTES);

    prep_kernel<<<32, 128>>>(cb);
    rvq_kernel<<<NBLOCKS, NTHREADS, SMEM_BYTES>>>(x, cb, out);
    finalize_kernel<<<1, 1>>>(out);
}

// round 15
// speedup vs baseline: 1.6259x; 1.6259x over previous
#include <cuda_runtime.h>
#include <cstdint>

// Problem constants
#define N_TOKENS 131072
#define E_DIM    128
#define KCB      1024
#define NQ       4

// Tiling
#define T_BLK    128
#define NTHREADS 512
#define CHUNK    128
#define NCHUNKS  8
#define NBLOCKS  1024
#define NCAND    4

#define XS_PITCH 129        // fp32 residual [t][k]
#define XQ_PITCH 129        // fp32 x_q [t][k]
#define QPITCH   36         // int8 rows as 36 words (144B)

// Output layout (float32): x_q [N,128] | mean_loss [1] | all_indices [N,4]
#define OUT_XQ_ELEMS   ((size_t)N_TOKENS * E_DIM)
#define OUT_LOSS_OFF   OUT_XQ_ELEMS
#define OUT_IDX_OFF    (OUT_XQ_ELEMS + 1)

// Smem layout (word offsets)
#define OFF_XS    0
#define OFF_XQ    16512
#define OFF_RR    33024
#define OFF_LOSS  33152
#define OFF_SA    33280     /* inv_sa = maxabs/127 */
#define OFF_S127  33408     /* 127/maxabs */
#define OFF_CCS   33536
#define OFF_RSS   33664
#define OFF_CAND  33792     /* 512 ints */
#define OFF_DEM   34304     /* 512 */
#define OFF_WIN   34816     /* 128 ints */
#define OFF_PA    34944     /* 128*9 = 1152 norm partials */
#define OFF_PM    36096     /* 128*5 = 640 maxabs partials */
#define OFF_QA    36736     /* 4608 words, 16B aligned */
#define OFF_QB    41344     /* 4608 words */
#define SM_TOTAL_F 45952
#define SMEM_BYTES (SM_TOTAL_F * 4)   /* 183808 B */

__device__ float    g_cc[NQ * KCB];                   // gold ||c||^2 (NEON emu)
__device__ float    g_rs[NQ * KCB];                   // maxabs_c / 127
__device__ uint32_t g_qb[NQ * KCB * 32];              // packed int8 codebook
__device__ float    g_partials[NBLOCKS];

// NEON-style vectorized sum-of-squares (XLA:CPU fast-math reduce) — VERIFIED bitwise vs ref.
__device__ __forceinline__ float neon_sumsq(const float* v) {
    float a0=0.f,a1=0.f,a2=0.f,a3=0.f,b0=0.f,b1=0.f,b2=0.f,b3=0.f;
    #pragma unroll 4
    for (int k = 0; k < E_DIM; k += 8) {
        float v0=v[k],v1=v[k+1],v2=v[k+2],v3=v[k+3],v4=v[k+4],v5=v[k+5],v6=v[k+6],v7=v[k+7];
        a0=__fmaf_rn(v0,v0,a0); a1=__fmaf_rn(v1,v1,a1); a2=__fmaf_rn(v2,v2,a2); a3=__fmaf_rn(v3,v3,a3);
        b0=__fmaf_rn(v4,v4,b0); b1=__fmaf_rn(v5,v5,b1); b2=__fmaf_rn(v6,v6,b2); b3=__fmaf_rn(v7,v7,b3);
    }
    float s0=__fadd_rn(a0,b0), s1=__fadd_rn(a1,b1), s2=__fadd_rn(a2,b2), s3=__fadd_rn(a3,b3);
    return __fadd_rn(__fadd_rn(s0,s1), __fadd_rn(s2,s3));
}

__device__ __forceinline__ uint32_t pack4(const float* v, float s) {
    int b0 = __float2int_rn(v[0] * s) & 255;
    int b1 = __float2int_rn(v[1] * s) & 255;
    int b2 = __float2int_rn(v[2] * s) & 255;
    int b3 = __float2int_rn(v[3] * s) & 255;
    return (uint32_t)(b0 | (b1 << 8) | (b2 << 16) | (b3 << 24));
}

__global__ void prep_kernel(const float* __restrict__ cb) {
    int c = blockIdx.x * blockDim.x + threadIdx.x;
    if (c < NQ * KCB) {
        const float* row = cb + (size_t)c * E_DIM;
        g_cc[c] = neon_sumsq(row);                    // gold
        float ma = 0.0f;
        #pragma unroll 8
        for (int k = 0; k < E_DIM; ++k) ma = fmaxf(ma, fabsf(row[k]));
        ma = fmaxf(ma, 1e-30f);
        g_rs[c] = ma * (1.0f / 127.0f);
        float s = 127.0f / ma;
        uint32_t* dst = g_qb + (size_t)c * 32;
        #pragma unroll 8
        for (int w = 0; w < 32; ++w) dst[w] = pack4(row + w * 4, s);
    }
}

__global__ void __launch_bounds__(NTHREADS, 1)
rvq_kernel(const float* __restrict__ x, const float* __restrict__ cb, float* __restrict__ out)
{
    extern __shared__ float sm[];
    float* xs      = sm + OFF_XS;
    float* xq      = sm + OFF_XQ;
    float* rr      = sm + OFF_RR;
    float* lossbuf = sm + OFF_LOSS;
    float* sainv   = sm + OFF_SA;
    float* s127    = sm + OFF_S127;
    float* ccs     = sm + OFF_CCS;
    float* rss     = sm + OFF_RSS;
    int*   cand    = (int*)(sm + OFF_CAND);
    float* dem     = sm + OFF_DEM;
    int*   win     = (int*)(sm + OFF_WIN);
    float* pa      = sm + OFF_PA;                    // [t][9] norm partials
    float* pm      = sm + OFF_PM;                    // [t][5] maxabs partials
    int*   qa      = (int*)(sm + OFF_QA);
    int*   qb      = (int*)(sm + OFF_QB);
    float* red_d   = sm + OFF_QA;                    // alias (post-GEMM): [t][32]
    int*   red_i   = (int*)(sm + OFF_QA + 4096);

    const int tid = threadIdx.x;
    const int tr  = tid & 31;      // lane -> token base
    const int tc  = tid >> 5;      // warp -> cw group tc*8..tc*8+7
    const int t0  = blockIdx.x * T_BLK;

    // ---- Load x tile (row-major), zero xq/lossbuf
    {
        const float4* x4 = (const float4*)(x + (size_t)t0 * E_DIM);
        #pragma unroll
        for (int r = 0; r < 8; ++r) {
            int f = tid + NTHREADS * r;
            int t = f >> 5, k4 = f & 31;
            float4 v = x4[f];
            xs[t * XS_PITCH + k4 * 4 + 0] = v.x;
            xs[t * XS_PITCH + k4 * 4 + 1] = v.y;
            xs[t * XS_PITCH + k4 * 4 + 2] = v.z;
            xs[t * XS_PITCH + k4 * 4 + 3] = v.w;
        }
        for (int o = tid; o < T_BLK * XQ_PITCH; o += NTHREADS) xq[o] = 0.0f;
        if (tid < T_BLK) lossbuf[tid] = 0.0f;
    }

    for (int s = 0; s <= NQ; ++s) {
        __syncthreads();
        // ---- phase 2: parallel NEON partials (4 threads/token, exact sub-chains)
        {
            int t = tid & 127, g = tid >> 7;         // g in 0..3
            const float* row = xs + t * XS_PITCH;
            float ag = 0.0f, bg = 0.0f, ma = 0.0f;
            #pragma unroll 16
            for (int k = g; k < E_DIM; k += 8) {     // k === g (mod 8)
                float v = row[k];
                ag = __fmaf_rn(v, v, ag);
                ma = fmaxf(ma, fabsf(v));
            }
            #pragma unroll 16
            for (int k = g + 4; k < E_DIM; k += 8) { // k === g+4 (mod 8)
                float v = row[k];
                bg = __fmaf_rn(v, v, bg);
                ma = fmaxf(ma, fabsf(v));
            }
            pa[t * 9 + g]     = ag;
            pa[t * 9 + 4 + g] = bg;
            pm[t * 5 + g]     = ma;
        }
        __syncthreads();
        // ---- phase 3: gold combine (bitwise == neon_sumsq)
        if (tid < T_BLK) {
            float s0 = __fadd_rn(pa[tid * 9 + 0], pa[tid * 9 + 4]);
            float s1 = __fadd_rn(pa[tid * 9 + 1], pa[tid * 9 + 5]);
            float s2 = __fadd_rn(pa[tid * 9 + 2], pa[tid * 9 + 6]);
            float s3 = __fadd_rn(pa[tid * 9 + 3], pa[tid * 9 + 7]);
            float a  = __fadd_rn(__fadd_rn(s0, s1), __fadd_rn(s2, s3));
            rr[tid] = a;
            if (s > 0) lossbuf[tid] += a;
            float ma = fmaxf(fmaxf(pm[tid * 5 + 0], pm[tid * 5 + 1]),
                             fmaxf(pm[tid * 5 + 2], pm[tid * 5 + 3]));
            ma = fmaxf(ma, 1e-30f);
            sainv[tid] = ma * (1.0f / 127.0f);
            s127[tid]  = 127.0f / ma;
        }
        __syncthreads();
        if (s == NQ) break;

        // ---- quantize residual to int8 (selection only)
        {
            int t = tid & 127, ks = (tid >> 7) * 32;
            float sc = s127[t];
            const float* row = xs + t * XS_PITCH + ks;
            int* dst = qa + t * QPITCH + ks / 4;
            #pragma unroll 8
            for (int w = 0; w < 8; ++w) dst[w] = (int)pack4(row + w * 4, sc);
        }

        // per-thread top-2 (token i handled = tr + 32*i)
        float d0[4], d1[4]; int i0[4], i1[4];
        #pragma unroll
        for (int i = 0; i < 4; ++i) {
            d0[i] = __int_as_float(0x7f800000); i0[i] = 0x7fffffff;
            d1[i] = __int_as_float(0x7f800000); i1[i] = 0x7fffffff;
        }

        // prefetch chunk 0 of B
        uint4 pre0, pre1; float ccp = 0.f, rsp = 0.f;
        {
            const uint4* src = (const uint4*)(g_qb + (size_t)s * KCB * 32);
            pre0 = src[tid]; pre1 = src[tid + 512];
            if (tid < CHUNK) { ccp = g_cc[s * KCB + tid]; rsp = g_rs[s * KCB + tid]; }
        }

        for (int ch = 0; ch < NCHUNKS; ++ch) {
            {
                int idx0 = tid, idx1 = tid + 512;
                *(uint4*)(qb + (idx0 >> 3) * QPITCH + (idx0 & 7) * 4) = pre0;
                *(uint4*)(qb + (idx1 >> 3) * QPITCH + (idx1 & 7) * 4) = pre1;
                if (tid < CHUNK) { ccs[tid] = ccp; rss[tid] = rsp; }
            }
            __syncthreads();

            if (ch + 1 < NCHUNKS) {
                const uint4* src = (const uint4*)(g_qb + ((size_t)s * KCB + (ch + 1) * CHUNK) * 32);
                pre0 = src[tid]; pre1 = src[tid + 512];
                if (tid < CHUNK) {
                    ccp = g_cc[s * KCB + (ch + 1) * CHUNK + tid];
                    rsp = g_rs[s * KCB + (ch + 1) * CHUNK + tid];
                }
            }

            // ---- int8 GEMM: 4 tok (stride-32) x 8 cw per thread via dp4a
            int acc[4][8];
            #pragma unroll
            for (int i = 0; i < 4; ++i)
                #pragma unroll
                for (int j = 0; j < 8; ++j) acc[i][j] = 0;

            #pragma unroll
            for (int k4 = 0; k4 < 8; ++k4) {
                uint4 b[8];
                #pragma unroll
                for (int j = 0; j < 8; ++j)
                    b[j] = *(const uint4*)(qb + (tc * 8 + j) * QPITCH + k4 * 4);
                #pragma unroll
                for (int i = 0; i < 4; ++i) {
                    uint4 a = *(const uint4*)(qa + (tr + 32 * i) * QPITCH + k4 * 4);
                    #pragma unroll
                    for (int j = 0; j < 8; ++j) {
                        acc[i][j] = __dp4a((int)a.x, (int)b[j].x, acc[i][j]);
                        acc[i][j] = __dp4a((int)a.y, (int)b[j].y, acc[i][j]);
                        acc[i][j] = __dp4a((int)a.z, (int)b[j].z, acc[i][j]);
                        acc[i][j] = __dp4a((int)a.w, (int)b[j].w, acc[i][j]);
                    }
                }
            }

            // ---- selection epilogue: v = cc - 2*inv_sa*rs[c]*dot  (rr cancels)
            #pragma unroll
            for (int i = 0; i < 4; ++i) {
                float t2 = 2.0f * sainv[tr + 32 * i];
                #pragma unroll
                for (int j = 0; j < 8; ++j) {
                    int   cl = tc * 8 + j;
                    float v  = __fmaf_rn(-t2, rss[cl] * (float)acc[i][j], ccs[cl]);
                    int   c  = ch * CHUNK + cl;
                    if (v < d0[i])      { d1[i]=d0[i]; i1[i]=i0[i]; d0[i]=v; i0[i]=c; }
                    else if (v < d1[i]) { d1[i]=v;     i1[i]=c; }
                }
            }
            __syncthreads();
        }

        // ---- dump per-thread top-2 (QA/QB dead -> red buffers)
        #pragma unroll
        for (int i = 0; i < 4; ++i) {
            int t = tr + 32 * i;
            red_d[t * 32 + tc * 2 + 0] = d0[i];
            red_d[t * 32 + tc * 2 + 1] = d1[i];
            red_i[t * 32 + tc * 2 + 0] = i0[i];
            red_i[t * 32 + tc * 2 + 1] = i1[i];
        }
        __syncthreads();

        // ---- merge 32 -> top-4 candidates
        if (tid < T_BLK) {
            float tv[NCAND]; int ti[NCAND];
            #pragma unroll
            for (int q = 0; q < NCAND; ++q) { tv[q] = __int_as_float(0x7f800000); ti[q] = 0x7fffffff; }
            for (int g = 0; g < 32; ++g) {
                float v = red_d[tid * 32 + g];
                int   c = red_i[tid * 32 + g];
                #pragma unroll
                for (int q = 0; q < NCAND; ++q) {
                    bool better = (v < tv[q]) || (v == tv[q] && c < ti[q]);
                    if (better) { float vt = tv[q]; int ct = ti[q]; tv[q] = v; ti[q] = c; v = vt; c = ct; }
                }
            }
            #pragma unroll
            for (int q = 0; q < NCAND; ++q) cand[tid * NCAND + q] = ti[q];
        }
        __syncthreads();

        // ---- gold refinement: 1 chain/thread, float4 loads, seq-FMA ascending (Eigen-consistent)
        {
            int t = tid & 127, q = tid >> 7;
            int c = cand[t * NCAND + q];
            const float4* crow4 = (const float4*)(cb + (size_t)(s * KCB + c) * E_DIM);
            const float*  xrow  = xs + t * XS_PITCH;
            float hs = 0.0f;
            #pragma unroll 8
            for (int w = 0; w < 32; ++w) {
                float4 f = crow4[w];
                hs = __fmaf_rn(xrow[w * 4 + 0], f.x, hs);
                hs = __fmaf_rn(xrow[w * 4 + 1], f.y, hs);
                hs = __fmaf_rn(xrow[w * 4 + 2], f.z, hs);
                hs = __fmaf_rn(xrow[w * 4 + 3], f.w, hs);
            }
            dem[t * NCAND + q] = __fadd_rn(__fsub_rn(rr[t], __fmul_rn(2.0f, hs)),
                                           g_cc[s * KCB + c]);
        }
        __syncthreads();

        // ---- winner pick (gold comparator)
        if (tid < T_BLK) {
            float bestv = 0.0f; int besti = -1;
            #pragma unroll
            for (int q = 0; q < NCAND; ++q) {
                int   c = cand[tid * NCAND + q];
                float v = dem[tid * NCAND + q];
                if (besti < 0 || v < bestv || (v == bestv && c < besti)) { bestv = v; besti = c; }
            }
            win[tid] = besti;
            out[OUT_IDX_OFF + (size_t)(t0 + tid) * NQ + s] = (float)besti;
        }
        __syncthreads();

        // ---- straight-through update (gold, elementwise), 512 threads
        {
            int t = tid >> 2, j = tid & 3;
            int besti = win[t];
            const float4* qrow = (const float4*)(cb + (size_t)(s * KCB + besti) * E_DIM);
            #pragma unroll
            for (int w = 0; w < 8; ++w) {
                int k4 = j * 8 + w;
                float4 q4 = qrow[k4];
                #pragma unroll
                for (int m = 0; m < 4; ++m) {
                    int   k  = k4 * 4 + m;
                    float qv = (m == 0) ? q4.x : (m == 1) ? q4.y : (m == 2) ? q4.z : q4.w;
                    float r  = xs[t * XS_PITCH + k];
                    float qt = __fadd_rn(r, __fsub_rn(qv, r));
                    xq[t * XQ_PITCH + k] = __fadd_rn(xq[t * XQ_PITCH + k], qt);
                    xs[t * XS_PITCH + k] = __fsub_rn(r, qt);
                }
            }
        }
    }

    if (tid == 0) {
        float a = 0.0f;
        for (int t = 0; t < T_BLK; ++t) a += lossbuf[t];
        g_partials[blockIdx.x] = a;
    }

    {
        float* o = out + (size_t)t0 * E_DIM;
        for (int f = tid; f < T_BLK * E_DIM; f += NTHREADS)
            o[f] = xq[(f >> 7) * XQ_PITCH + (f & 127)];
    }
}

__global__ void finalize_kernel(float* __restrict__ out) {
    if (threadIdx.x == 0 && blockIdx.x == 0) {
        double a = 0.0;
        for (int i = 0; i < NBLOCKS; ++i) a += (double)g_partials[i];
        out[OUT_LOSS_OFF] = (float)(a * (0.25 / (4.0 * (double)N_TOKENS * (double)E_DIM)));
    }
}

extern "C" void kernel_launch(void* const* d_in, const int* in_sizes, int n_in,
                              void* d_out, int out_size) {
    (void)in_sizes; (void)n_in; (void)out_size;
    const float* x  = (const float*)d_in[0];
    const float* cb = (const float*)d_in[1];
    float* out = (float*)d_out;

    cudaFuncSetAttribute(rvq_kernel, cudaFuncAttributeMaxDynamicSharedMemorySize, SMEM_BYTES);

    prep_kernel<<<32, 128>>>(cb);
    rvq_kernel<<<NBLOCKS, NTHREADS, SMEM_BYTES>>>(x, cb, out);
    finalize_kernel<<<1, 1>>>(out);
}

// round 16
// speedup vs baseline: 1.8544x; 1.1405x over previous
#include <cuda_runtime.h>
#include <cstdint>

// Problem constants
#define N_TOKENS 131072
#define E_DIM    128
#define KCB      1024
#define NQ       4

// Tiling
#define T_BLK    128
#define NTHREADS 512
#define CHUNK    128
#define NCHUNKS  8
#define NBLOCKS  1024
#define NCAND    4

#define XS_PITCH 129        // fp32 residual [t][k]
#define XQ_PITCH 129        // fp32 x_q [t][k]
#define QPITCH   36         // int8 rows as 36 words (144B)

// Output layout (float32): x_q [N,128] | mean_loss [1] | all_indices [N,4]
#define OUT_XQ_ELEMS   ((size_t)N_TOKENS * E_DIM)
#define OUT_LOSS_OFF   OUT_XQ_ELEMS
#define OUT_IDX_OFF    (OUT_XQ_ELEMS + 1)

// Smem layout (word offsets)
#define OFF_XS    0
#define OFF_XQ    16512
#define OFF_RR    33024
#define OFF_LOSS  33152
#define OFF_SA    33280     /* inv_sa = maxabs/127 */
#define OFF_S127  33408     /* 127/maxabs */
#define OFF_CCS   33536     /* 2 x 128 (double buffered) */
#define OFF_RSS   33792     /* 2 x 128 */
#define OFF_CAND  34048     /* 512 ints */
#define OFF_DEM   34560     /* 512 */
#define OFF_WIN   35072     /* 128 ints */
#define OFF_PA    35200     /* 128*9 norm partials */
#define OFF_PM    36352     /* 128*5 maxabs partials */
#define OFF_QA    37120     /* 4608 words, 16B aligned */
#define OFF_QB0   41728     /* 4608 words */
#define OFF_QB1   46336     /* 4608 words */
#define SM_TOTAL_F 50944
#define SMEM_BYTES (SM_TOTAL_F * 4)   /* 203776 B */

__device__ float    g_cc[NQ * KCB];                   // gold ||c||^2 (NEON emu)
__device__ float    g_rs[NQ * KCB];                   // maxabs_c / 127
__device__ uint32_t g_qb[NQ * KCB * 32];              // packed int8 codebook
__device__ float    g_partials[NBLOCKS];
__device__ int      g_ctr;                            // finalize counter (self-resetting)

// NEON-style vectorized sum-of-squares (XLA:CPU fast-math reduce) — VERIFIED bitwise vs ref.
__device__ __forceinline__ float neon_sumsq(const float* v) {
    float a0=0.f,a1=0.f,a2=0.f,a3=0.f,b0=0.f,b1=0.f,b2=0.f,b3=0.f;
    #pragma unroll 4
    for (int k = 0; k < E_DIM; k += 8) {
        float v0=v[k],v1=v[k+1],v2=v[k+2],v3=v[k+3],v4=v[k+4],v5=v[k+5],v6=v[k+6],v7=v[k+7];
        a0=__fmaf_rn(v0,v0,a0); a1=__fmaf_rn(v1,v1,a1); a2=__fmaf_rn(v2,v2,a2); a3=__fmaf_rn(v3,v3,a3);
        b0=__fmaf_rn(v4,v4,b0); b1=__fmaf_rn(v5,v5,b1); b2=__fmaf_rn(v6,v6,b2); b3=__fmaf_rn(v7,v7,b3);
    }
    float s0=__fadd_rn(a0,b0), s1=__fadd_rn(a1,b1), s2=__fadd_rn(a2,b2), s3=__fadd_rn(a3,b3);
    return __fadd_rn(__fadd_rn(s0,s1), __fadd_rn(s2,s3));
}

__device__ __forceinline__ uint32_t pack4(const float* v, float s) {
    int b0 = __float2int_rn(v[0] * s) & 255;
    int b1 = __float2int_rn(v[1] * s) & 255;
    int b2 = __float2int_rn(v[2] * s) & 255;
    int b3 = __float2int_rn(v[3] * s) & 255;
    return (uint32_t)(b0 | (b1 << 8) | (b2 << 16) | (b3 << 24));
}

// float -> order-preserving uint32 (total order; equal floats -> equal keys)
__device__ __forceinline__ uint32_t ord32(float v) {
    uint32_t b = __float_as_uint(v);
    return b ^ ((uint32_t)((int)b >> 31) | 0x80000000u);
}

__global__ void prep_kernel(const float* __restrict__ cb) {
    int c = blockIdx.x * blockDim.x + threadIdx.x;
    if (c < NQ * KCB) {
        const float* row = cb + (size_t)c * E_DIM;
        g_cc[c] = neon_sumsq(row);                    // gold
        float ma = 0.0f;
        #pragma unroll 8
        for (int k = 0; k < E_DIM; ++k) ma = fmaxf(ma, fabsf(row[k]));
        ma = fmaxf(ma, 1e-30f);
        g_rs[c] = ma * (1.0f / 127.0f);
        float s = 127.0f / ma;
        uint32_t* dst = g_qb + (size_t)c * 32;
        #pragma unroll 8
        for (int w = 0; w < 32; ++w) dst[w] = pack4(row + w * 4, s);
    }
}

__global__ void __launch_bounds__(NTHREADS, 1)
rvq_kernel(const float* __restrict__ x, const float* __restrict__ cb, float* __restrict__ out)
{
    extern __shared__ float sm[];
    float* xs      = sm + OFF_XS;
    float* xq      = sm + OFF_XQ;
    float* rr      = sm + OFF_RR;
    float* lossbuf = sm + OFF_LOSS;
    float* sainv   = sm + OFF_SA;
    float* s127    = sm + OFF_S127;
    float* ccs     = sm + OFF_CCS;     // [2][128]
    float* rss     = sm + OFF_RSS;     // [2][128]
    int*   cand    = (int*)(sm + OFF_CAND);
    float* dem     = sm + OFF_DEM;
    int*   win     = (int*)(sm + OFF_WIN);
    float* pa      = sm + OFF_PA;
    float* pm      = sm + OFF_PM;
    int*   qa      = (int*)(sm + OFF_QA);
    uint32_t* redk = (uint32_t*)(sm + OFF_QA);        // alias (post-GEMM): [t][32] keys

    const int tid = threadIdx.x;
    const int tr  = tid & 31;      // lane -> token base
    const int tc  = tid >> 5;      // warp -> cw group tc*8..tc*8+7
    const int t0  = blockIdx.x * T_BLK;

    // ---- Load x tile (row-major), zero xq/lossbuf
    {
        const float4* x4 = (const float4*)(x + (size_t)t0 * E_DIM);
        #pragma unroll
        for (int r = 0; r < 8; ++r) {
            int f = tid + NTHREADS * r;
            int t = f >> 5, k4 = f & 31;
            float4 v = x4[f];
            xs[t * XS_PITCH + k4 * 4 + 0] = v.x;
            xs[t * XS_PITCH + k4 * 4 + 1] = v.y;
            xs[t * XS_PITCH + k4 * 4 + 2] = v.z;
            xs[t * XS_PITCH + k4 * 4 + 3] = v.w;
        }
        for (int o = tid; o < T_BLK * XQ_PITCH; o += NTHREADS) xq[o] = 0.0f;
        if (tid < T_BLK) lossbuf[tid] = 0.0f;
    }

    for (int s = 0; s <= NQ; ++s) {
        __syncthreads();
        // ---- parallel NEON partials (4 threads/token, exact sub-chains)
        {
            int t = tid & 127, g = tid >> 7;
            const float* row = xs + t * XS_PITCH;
            float ag = 0.0f, bg = 0.0f, ma = 0.0f;
            #pragma unroll 16
            for (int k = g; k < E_DIM; k += 8) {
                float v = row[k]; ag = __fmaf_rn(v, v, ag); ma = fmaxf(ma, fabsf(v));
            }
            #pragma unroll 16
            for (int k = g + 4; k < E_DIM; k += 8) {
                float v = row[k]; bg = __fmaf_rn(v, v, bg); ma = fmaxf(ma, fabsf(v));
            }
            pa[t * 9 + g]     = ag;
            pa[t * 9 + 4 + g] = bg;
            pm[t * 5 + g]     = ma;
        }
        __syncthreads();
        // ---- gold combine (bitwise == neon_sumsq)
        if (tid < T_BLK) {
            float s0 = __fadd_rn(pa[tid * 9 + 0], pa[tid * 9 + 4]);
            float s1 = __fadd_rn(pa[tid * 9 + 1], pa[tid * 9 + 5]);
            float s2 = __fadd_rn(pa[tid * 9 + 2], pa[tid * 9 + 6]);
            float s3 = __fadd_rn(pa[tid * 9 + 3], pa[tid * 9 + 7]);
            float a  = __fadd_rn(__fadd_rn(s0, s1), __fadd_rn(s2, s3));
            rr[tid] = a;
            if (s > 0) lossbuf[tid] += a;
            float ma = fmaxf(fmaxf(pm[tid * 5 + 0], pm[tid * 5 + 1]),
                             fmaxf(pm[tid * 5 + 2], pm[tid * 5 + 3]));
            ma = fmaxf(ma, 1e-30f);
            sainv[tid] = ma * (1.0f / 127.0f);
            s127[tid]  = 127.0f / ma;
        }
        __syncthreads();
        if (s == NQ) break;

        // ---- quantize residual to int8 (selection only)
        {
            int t = tid & 127, ks = (tid >> 7) * 32;
            float sc = s127[t];
            const float* row = xs + t * XS_PITCH + ks;
            int* dst = qa + t * QPITCH + ks / 4;
            #pragma unroll 8
            for (int w = 0; w < 8; ++w) dst[w] = (int)pack4(row + w * 4, sc);
        }

        // per-thread top-2 keys (token i = tr + 32*i); key = ord22(v)|c
        uint32_t s0k[4], s1k[4];
        #pragma unroll
        for (int i = 0; i < 4; ++i) { s0k[i] = 0xFFFFFFFFu; s1k[i] = 0xFFFFFFFFu; }

        // prefetch chunk 0 of B
        uint4 pre0, pre1; float ccp = 0.f, rsp = 0.f;
        {
            const uint4* src = (const uint4*)(g_qb + (size_t)s * KCB * 32);
            pre0 = src[tid]; pre1 = src[tid + 512];
            if (tid < CHUNK) { ccp = g_cc[s * KCB + tid]; rsp = g_rs[s * KCB + tid]; }
        }
        // commit chunk 0 into buffer 0
        {
            int* qb0 = (int*)(sm + OFF_QB0);
            *(uint4*)(qb0 + (tid >> 3) * QPITCH + (tid & 7) * 4) = pre0;
            int idx1 = tid + 512;
            *(uint4*)(qb0 + (idx1 >> 3) * QPITCH + (idx1 & 7) * 4) = pre1;
            if (tid < CHUNK) { ccs[tid] = ccp; rss[tid] = rsp; }
        }
        __syncthreads();

        for (int ch = 0; ch < NCHUNKS; ++ch) {
            const int cur = ch & 1;
            int* qb = (int*)(sm + (cur ? OFF_QB1 : OFF_QB0));

            // prefetch next chunk from gmem
            if (ch + 1 < NCHUNKS) {
                const uint4* src = (const uint4*)(g_qb + ((size_t)s * KCB + (ch + 1) * CHUNK) * 32);
                pre0 = src[tid]; pre1 = src[tid + 512];
                if (tid < CHUNK) {
                    ccp = g_cc[s * KCB + (ch + 1) * CHUNK + tid];
                    rsp = g_rs[s * KCB + (ch + 1) * CHUNK + tid];
                }
            }

            // ---- int8 GEMM: 4 tok (stride-32) x 8 cw per thread via dp4a
            int acc[4][8];
            #pragma unroll
            for (int i = 0; i < 4; ++i)
                #pragma unroll
                for (int j = 0; j < 8; ++j) acc[i][j] = 0;

            #pragma unroll
            for (int k4 = 0; k4 < 8; ++k4) {
                uint4 b[8];
                #pragma unroll
                for (int j = 0; j < 8; ++j)
                    b[j] = *(const uint4*)(qb + (tc * 8 + j) * QPITCH + k4 * 4);
                #pragma unroll
                for (int i = 0; i < 4; ++i) {
                    uint4 a = *(const uint4*)(qa + (tr + 32 * i) * QPITCH + k4 * 4);
                    #pragma unroll
                    for (int j = 0; j < 8; ++j) {
                        acc[i][j] = __dp4a((int)a.x, (int)b[j].x, acc[i][j]);
                        acc[i][j] = __dp4a((int)a.y, (int)b[j].y, acc[i][j]);
                        acc[i][j] = __dp4a((int)a.z, (int)b[j].z, acc[i][j]);
                        acc[i][j] = __dp4a((int)a.w, (int)b[j].w, acc[i][j]);
                    }
                }
            }

            // ---- branchless selection epilogue: key = (ord(v)&~1023)|c, top-2 via umin/umax
            const float* ccb = ccs + cur * CHUNK;
            const float* rsb = rss + cur * CHUNK;
            #pragma unroll
            for (int i = 0; i < 4; ++i) {
                float t2 = 2.0f * sainv[tr + 32 * i];
                #pragma unroll
                for (int j = 0; j < 8; ++j) {
                    int   cl = tc * 8 + j;
                    float v  = __fmaf_rn(-t2, rsb[cl] * (float)acc[i][j], ccb[cl]);
                    uint32_t key = (ord32(v) & 0xFFFFFC00u) | (uint32_t)(ch * CHUNK + cl);
                    uint32_t lo = umin(s0k[i], key);
                    uint32_t hi = umax(s0k[i], key);
                    s0k[i] = lo;
                    s1k[i] = umin(s1k[i], hi);
                }
            }

            // commit prefetched chunk into other buffer, then one sync
            if (ch + 1 < NCHUNKS) {
                int* qbn = (int*)(sm + (cur ? OFF_QB0 : OFF_QB1));
                *(uint4*)(qbn + (tid >> 3) * QPITCH + (tid & 7) * 4) = pre0;
                int idx1 = tid + 512;
                *(uint4*)(qbn + (idx1 >> 3) * QPITCH + (idx1 & 7) * 4) = pre1;
                if (tid < CHUNK) {
                    ccs[(cur ^ 1) * CHUNK + tid] = ccp;
                    rss[(cur ^ 1) * CHUNK + tid] = rsp;
                }
            }
            __syncthreads();
        }

        // ---- dump per-thread top-2 keys (QA dead -> red buffer)
        #pragma unroll
        for (int i = 0; i < 4; ++i) {
            int t = tr + 32 * i;
            redk[t * 32 + tc * 2 + 0] = s0k[i];
            redk[t * 32 + tc * 2 + 1] = s1k[i];
        }
        __syncthreads();

        // ---- branchless merge 32 keys -> top-4 candidates
        if (tid < T_BLK) {
            uint32_t tk[NCAND];
            #pragma unroll
            for (int q = 0; q < NCAND; ++q) tk[q] = 0xFFFFFFFFu;
            #pragma unroll 4
            for (int g = 0; g < 32; ++g) {
                uint32_t k = redk[tid * 32 + g];
                #pragma unroll
                for (int q = 0; q < NCAND; ++q) {
                    uint32_t lo = umin(tk[q], k);
                    k = umax(tk[q], k);
                    tk[q] = lo;
                }
            }
            #pragma unroll
            for (int q = 0; q < NCAND; ++q) cand[tid * NCAND + q] = (int)(tk[q] & 1023u);
        }
        __syncthreads();

        // ---- gold refinement: 1 chain/thread, float4 loads, seq-FMA ascending (Eigen-consistent)
        {
            int t = tid & 127, q = tid >> 7;
            int c = cand[t * NCAND + q];
            const float4* crow4 = (const float4*)(cb + (size_t)(s * KCB + c) * E_DIM);
            const float*  xrow  = xs + t * XS_PITCH;
            float hs = 0.0f;
            #pragma unroll 8
            for (int w = 0; w < 32; ++w) {
                float4 f = crow4[w];
                hs = __fmaf_rn(xrow[w * 4 + 0], f.x, hs);
                hs = __fmaf_rn(xrow[w * 4 + 1], f.y, hs);
                hs = __fmaf_rn(xrow[w * 4 + 2], f.z, hs);
                hs = __fmaf_rn(xrow[w * 4 + 3], f.w, hs);
            }
            dem[t * NCAND + q] = __fadd_rn(__fsub_rn(rr[t], __fmul_rn(2.0f, hs)),
                                           g_cc[s * KCB + c]);
        }
        __syncthreads();

        // ---- winner pick: exact gold comparator via u64 key min (branchless)
        if (tid < T_BLK) {
            unsigned long long best = ~0ull;
            #pragma unroll
            for (int q = 0; q < NCAND; ++q) {
                int c = cand[tid * NCAND + q];
                unsigned long long k =
                    ((unsigned long long)ord32(dem[tid * NCAND + q]) << 10) | (unsigned)c;
                best = (k < best) ? k : best;
            }
            int besti = (int)(best & 1023ull);
            win[tid] = besti;
            out[OUT_IDX_OFF + (size_t)(t0 + tid) * NQ + s] = (float)besti;
        }
        __syncthreads();

        // ---- straight-through update (gold, elementwise), 512 threads
        {
            int t = tid >> 2, j = tid & 3;
            int besti = win[t];
            const float4* qrow = (const float4*)(cb + (size_t)(s * KCB + besti) * E_DIM);
            #pragma unroll
            for (int w = 0; w < 8; ++w) {
                int k4 = j * 8 + w;
                float4 q4 = qrow[k4];
                #pragma unroll
                for (int m = 0; m < 4; ++m) {
                    int   k  = k4 * 4 + m;
                    float qv = (m == 0) ? q4.x : (m == 1) ? q4.y : (m == 2) ? q4.z : q4.w;
                    float r  = xs[t * XS_PITCH + k];
                    float qt = __fadd_rn(r, __fsub_rn(qv, r));
                    xq[t * XQ_PITCH + k] = __fadd_rn(xq[t * XQ_PITCH + k], qt);
                    xs[t * XS_PITCH + k] = __fsub_rn(r, qt);
                }
            }
        }
    }

    if (tid == 0) {
        float a = 0.0f;
        for (int t = 0; t < T_BLK; ++t) a += lossbuf[t];
        g_partials[blockIdx.x] = a;
    }

    {
        float* o = out + (size_t)t0 * E_DIM;
        for (int f = tid; f < T_BLK * E_DIM; f += NTHREADS)
            o[f] = xq[(f >> 7) * XQ_PITCH + (f & 127)];
    }

    // ---- fused finalize: last block sums partials in fixed order (deterministic)
    __threadfence();
    __syncthreads();
    if (tid == 0) {
        int v = atomicAdd(&g_ctr, 1);
        if (v == NBLOCKS - 1) {
            __threadfence();
            volatile float* p = g_partials;
            double a = 0.0;
            for (int i = 0; i < NBLOCKS; ++i) a += (double)p[i];
            out[OUT_LOSS_OFF] = (float)(a * (0.25 / (4.0 * (double)N_TOKENS * (double)E_DIM)));
            g_ctr = 0;   // reset for next (graph-replayed) launch
        }
    }
}

extern "C" void kernel_launch(void* const* d_in, const int* in_sizes, int n_in,
                              void* d_out, int out_size) {
    (void)in_sizes; (void)n_in; (void)out_size;
    const float* x  = (const float*)d_in[0];
    const float* cb = (const float*)d_in[1];
    float* out = (float*)d_out;

    cudaFuncSetAttribute(rvq_kernel, cudaFuncAttributeMaxDynamicSharedMemorySize, SMEM_BYTES);

    prep_kernel<<<32, 128>>>(cb);
    rvq_kernel<<<NBLOCKS, NTHREADS, SMEM_BYTES>>>(x, cb, out);
}